// round 17
// baseline (speedup 1.0000x reference)
#include <cuda_runtime.h>
#include <cuda_fp16.h>
#include <cuda_bf16.h>

#define NN 4
#define NQ 256
#define NV 512
#define NE 256

// Scratch (allocation-free requirement)
__device__ float g_expl[NN * NQ * NV];       // exp(logit/t)  (2 MB)
__device__ float g_denp[NN * NQ * 8];        // per-64v denominator partials
__device__ float g_heads[NN * NQ * NE];      // normalized, leaky heads (1 MB)

// ---------------------------------------------------------------------------
// helpers
// ---------------------------------------------------------------------------
__device__ __forceinline__ uint4 pack8(const float4 a, const float4 b) {
    __half2 h0 = __floats2half2_rn(a.x, a.y);
    __half2 h1 = __floats2half2_rn(a.z, a.w);
    __half2 h2 = __floats2half2_rn(b.x, b.y);
    __half2 h3 = __floats2half2_rn(b.z, b.w);
    uint4 r;
    r.x = *reinterpret_cast<unsigned*>(&h0);
    r.y = *reinterpret_cast<unsigned*>(&h1);
    r.z = *reinterpret_cast<unsigned*>(&h2);
    r.w = *reinterpret_cast<unsigned*>(&h3);
    return r;
}

__device__ __forceinline__ __half2 u2h(unsigned u) {
    return *reinterpret_cast<__half2*>(&u);
}

// tanh of (q+c) in f16x2, times w (f16x2)
__device__ __forceinline__ __half2 wtanh(unsigned cv, unsigned qv, unsigned wv) {
    __half2 s = __hadd2(u2h(qv), u2h(cv));
    unsigned su = *reinterpret_cast<unsigned*>(&s);
    unsigned tu;
    asm("tanh.approx.f16x2 %0, %1;" : "=r"(tu) : "r"(su));
    return __hmul2(u2h(tu), u2h(wv));
}

// ---------------------------------------------------------------------------
// K1: e[n,q,v] = exp( (sum_e w*tanh(q+c) + b) / t ), plus per-64v denom
// partials. EXACT champion body (measured 59.7/59.9/59.9; MUFU floor).
// ---------------------------------------------------------------------------
__global__ void __launch_bounds__(256) k_logits(
    const float* __restrict__ q, const float* __restrict__ c,
    const float* __restrict__ wl, const float* __restrict__ bl_p,
    const float* __restrict__ temp_p)
{
    __shared__ uint4 ct[32][33];    // 16.9 KB, [e-octet][v]
    __shared__ uint4 qs[8][32];     // 4 KB
    __shared__ uint4 ws[32];        // 512 B

    const int n = blockIdx.z;
    const int qbase = blockIdx.x * 8;
    const int tid = threadIdx.x;
    const int wq = tid >> 5, lane = tid & 31;

    {   // one q-octet per thread
        int r = tid >> 5, g = tid & 31;
        const float4* src =
            (const float4*)&q[((size_t)n * NQ + qbase + r) * NE + g * 8];
        qs[r][g] = pack8(src[0], src[1]);
    }
    if (tid < 32) {
        const float4* src = (const float4*)&wl[tid * 8];
        ws[tid] = pack8(src[0], src[1]);
    }
    const float bl = __ldg(bl_p);
    const float invt = 1.0f / __ldg(temp_p);

    float dsum = 0.f;
    #pragma unroll
    for (int t = 0; t < 2; ++t) {
        __syncthreads();
        const int vbase = blockIdx.y * 64 + t * 32;
        for (int i = tid; i < 1024; i += 256) {   // 32 v x 32 octets
            int v = i >> 5, g = i & 31;
            const float4* src =
                (const float4*)&c[((size_t)n * NV + vbase + v) * NE + g * 8];
            ct[g][v] = pack8(src[0], src[1]);
        }
        __syncthreads();

        float a0 = 0.f, a1 = 0.f;
        #pragma unroll 8
        for (int g = 0; g < 32; ++g) {
            uint4 cb = ct[g][lane];
            uint4 qb = qs[wq][g];
            uint4 wb = ws[g];
            __half2 p0 = wtanh(cb.x, qb.x, wb.x);
            __half2 p1 = wtanh(cb.y, qb.y, wb.y);
            __half2 p2 = wtanh(cb.z, qb.z, wb.z);
            __half2 p3 = wtanh(cb.w, qb.w, wb.w);
            __half2 ps = __hadd2(__hadd2(p0, p1), __hadd2(p2, p3));
            float2 f = __half22float2(ps);
            a0 += f.x;
            a1 += f.y;
        }
        float e = __expf((a0 + a1 + bl) * invt);
        dsum += e;
        g_expl[((size_t)n * NQ + qbase + wq) * NV + vbase + lane] = e;
    }

    // warp-reduce dsum over 32 lanes (this block's 64 v's for row wq)
    #pragma unroll
    for (int o = 16; o; o >>= 1) dsum += __shfl_xor_sync(0xffffffffu, dsum, o);
    if (lane == 0)
        g_denp[((size_t)n * NQ + qbase + wq) * 8 + blockIdx.y] = dsum;
}

// ---------------------------------------------------------------------------
// K2: heads = leaky( softmax-probs @ memory ).  n-split (no K split):
// 32x32 output tiles, full K=512 per block, grid 8x8x4 = 256 blocks.
// Normalization fused into A-staging (row inv fixed per staging thread);
// leaky in epilogue. Writes g_heads directly — no partials, no merge.
// ---------------------------------------------------------------------------
__global__ void __launch_bounds__(256) k_pv(const float* __restrict__ Mm)
{
    const int n = blockIdx.z;
    const int m0 = blockIdx.y * 32, n0 = blockIdx.x * 32;
    const float* A = g_expl + (size_t)n * NQ * NV;   // [256][512]
    const float* B = Mm + (size_t)n * NV * NE;       // [512][256]

    __shared__ float As[16][36];   // [k][m]
    __shared__ float Bs[16][36];   // [k][n]

    const int tid = threadIdx.x;
    const int tx = tid & 15, ty = tid >> 4;          // 2n x 2m micro
    const int ar = tid >> 3, ac = (tid & 7) * 2;     // A: 32 rows x 16 k
    const int bkr = tid >> 4, bnc = (tid & 15) * 2;  // B: 16 k x 32 n

    // softmax denominator inverse for staging row (fixed per thread)
    float dt = 0.f;
    #pragma unroll
    for (int vb = 0; vb < 8; ++vb)
        dt += g_denp[((size_t)n * NQ + m0 + ar) * 8 + vb];
    const float inv = 1.0f / dt;

    float acc[2][2] = {};

    for (int k0 = 0; k0 < NV; k0 += 16) {
        float2 av = *(const float2*)&A[(size_t)(m0 + ar) * NV + k0 + ac];
        As[ac][ar]     = av.x * inv;
        As[ac + 1][ar] = av.y * inv;
        *(float2*)&Bs[bkr][bnc] =
            *(const float2*)&B[(size_t)(k0 + bkr) * NE + n0 + bnc];
        __syncthreads();
        #pragma unroll
        for (int k = 0; k < 16; ++k) {
            float2 a = *(const float2*)&As[k][ty * 2];
            float2 b = *(const float2*)&Bs[k][tx * 2];
            acc[0][0] += a.x * b.x;
            acc[0][1] += a.x * b.y;
            acc[1][0] += a.y * b.x;
            acc[1][1] += a.y * b.y;
        }
        __syncthreads();
    }

    float* H = g_heads + (size_t)n * NQ * NE;
    #pragma unroll
    for (int i = 0; i < 2; ++i) {
        float h0 = acc[i][0], h1 = acc[i][1];
        h0 = (h0 > 0.f) ? h0 : 0.01f * h0;
        h1 = (h1 > 0.f) ? h1 : 0.01f * h1;
        *(float2*)&H[(size_t)(m0 + ty * 2 + i) * NE + n0 + tx * 2] =
            make_float2(h0, h1);
    }
}

// ---------------------------------------------------------------------------
// K3: out = heads @ Wr^T + bias.  Same shape: 32x32 tiles, K=256 unsplit,
// grid 8x8x4 = 256 blocks, bias fused, writes out directly.
// ---------------------------------------------------------------------------
__global__ void __launch_bounds__(256) k_out(
    const float* __restrict__ Wr, const float* __restrict__ br_p,
    float* __restrict__ out)
{
    const int n = blockIdx.z;
    const int m0 = blockIdx.y * 32, n0 = blockIdx.x * 32;
    const float* A = g_heads + (size_t)n * NQ * NE;

    __shared__ float As[16][36];   // [k][m]
    __shared__ float Bs[16][36];   // [k][j]

    const int tid = threadIdx.x;
    const int tx = tid & 15, ty = tid >> 4;
    const int ar = tid >> 3, ac = (tid & 7) * 2;   // 32 rows x 16 k

    float acc[2][2] = {};

    for (int k0 = 0; k0 < NE; k0 += 16) {
        float2 av = *(const float2*)&A[(size_t)(m0 + ar) * NE + k0 + ac];
        As[ac][ar]     = av.x;
        As[ac + 1][ar] = av.y;
        // Bs[k][j] = Wr[(n0+j)*NE + k0+k]  (transpose during staging)
        float2 wv = *(const float2*)&Wr[(size_t)(n0 + ar) * NE + k0 + ac];
        Bs[ac][ar]     = wv.x;
        Bs[ac + 1][ar] = wv.y;
        __syncthreads();
        #pragma unroll
        for (int k = 0; k < 16; ++k) {
            float2 a = *(const float2*)&As[k][ty * 2];
            float2 b = *(const float2*)&Bs[k][tx * 2];
            acc[0][0] += a.x * b.x;
            acc[0][1] += a.x * b.y;
            acc[1][0] += a.y * b.x;
            acc[1][1] += a.y * b.y;
        }
        __syncthreads();
    }

    float2 b2 = *(const float2*)&br_p[n0 + tx * 2];
    #pragma unroll
    for (int i = 0; i < 2; ++i) {
        *(float2*)&out[((size_t)n * NQ + m0 + ty * 2 + i) * NE + n0 + tx * 2] =
            make_float2(acc[i][0] + b2.x, acc[i][1] + b2.y);
    }
}

// ---------------------------------------------------------------------------
extern "C" void kernel_launch(void* const* d_in, const int* in_sizes, int n_in,
                              void* d_out, int out_size)
{
    const float* query   = (const float*)d_in[0];
    const float* context = (const float*)d_in[1];
    const float* memory  = (const float*)d_in[2];
    const float* w_logit = (const float*)d_in[3];
    const float* b_logit = (const float*)d_in[4];
    const float* temp    = (const float*)d_in[5];
    const float* w_red   = (const float*)d_in[6];
    const float* b_red   = (const float*)d_in[7];
    float* out = (float*)d_out;

    dim3 g1(NQ / 8, NV / 64, NN);        // 32 x 8 x 4 = 1024 blocks
    k_logits<<<g1, 256>>>(query, context, w_logit, b_logit, temp);

    dim3 g2(NE / 32, NQ / 32, NN);       // 8 x 8 x 4 = 256 blocks
    k_pv<<<g2, 256>>>(memory);

    dim3 g3(NE / 32, NQ / 32, NN);       // 256 blocks
    k_out<<<g3, 256>>>(w_red, b_red, out);
}